// round 9
// baseline (speedup 1.0000x reference)
#include <cuda_runtime.h>
#include <cuda_fp16.h>

// HashEmbedding: out[t, d] = sum_{h=0..3} weight_table[x[t,h] + 513*h] * emb_table[x[t,h]>>1][d]
// x is int32.
// R9: R7 base (fp16 full table in smem, sync-free warp-per-token) + DEPTH-3
// rotating prefetch of the x index loads. R6-R8 show no unit above 41%: the
// kernel stalls on the loop-carried index LDG (L2/DRAM, 250-577 cyc) that
// depth-1 prefetch cannot cover. Streaming hints on x loads and out stores.

#define NUM_HASHES 4
#define D 256
#define W_TABLE 2052           // 512*4 + 4
#define EMB_ROWS 256
#define BLOCK_THREADS 1024
#define WARPS_PER_BLOCK (BLOCK_THREADS / 32)
#define GRID_X 148

// smem byte offsets
#define OFF_W     0
#define OFF_EMB   ((W_TABLE * 4 + 15) & ~15)                 // 8208
#define SMEM_BYTES (OFF_EMB + EMB_ROWS * D * 2)              // + 128 KB

__device__ __forceinline__ int4 ldcs_int4(const int* p) {
    int4 v;
    asm volatile("ld.global.cs.v4.s32 {%0,%1,%2,%3}, [%4];"
                 : "=r"(v.x), "=r"(v.y), "=r"(v.z), "=r"(v.w)
                 : "l"(p));
    return v;
}

__device__ __forceinline__ void stcs_float4(float* p, float4 v) {
    asm volatile("st.global.cs.v4.f32 [%0], {%1,%2,%3,%4};"
                 :: "l"(p), "f"(v.x), "f"(v.y), "f"(v.z), "f"(v.w)
                 : "memory");
}

__global__ __launch_bounds__(BLOCK_THREADS, 1)
void hash_embedding_kernel(const int* __restrict__ x,
                           const float* __restrict__ weight_table,
                           const float* __restrict__ emb_table,
                           float* __restrict__ out,
                           int ntok)
{
    extern __shared__ char smem[];
    float* s_w   = reinterpret_cast<float*>(smem + OFF_W);
    char*  s_emb = smem + OFF_EMB;          // [256 rows][256 halves] = 512 B/row

    const int tid = threadIdx.x;

    // ---- prologue: stage weight table (f32) ----
    for (int i = tid; i < W_TABLE; i += BLOCK_THREADS) s_w[i] = weight_table[i];

    // ---- prologue: stage emb table converted to fp16 ----
    for (int i = tid; i < EMB_ROWS * D / 4; i += BLOCK_THREADS) {
        const int r  = i >> 6;          // row
        const int c4 = i & 63;          // float4 group within row
        const float4 v = *reinterpret_cast<const float4*>(emb_table + r * D + c4 * 4);
        __half2 h0 = __floats2half2_rn(v.x, v.y);
        __half2 h1 = __floats2half2_rn(v.z, v.w);
        uint2 packed;
        packed.x = *reinterpret_cast<unsigned int*>(&h0);
        packed.y = *reinterpret_cast<unsigned int*>(&h1);
        *reinterpret_cast<uint2*>(s_emb + r * 512 + c4 * 8) = packed;
    }
    __syncthreads();   // the ONLY block-wide sync in the kernel

    const int lane = tid & 31;
    const int gw   = blockIdx.x * WARPS_PER_BLOCK + (tid >> 5);  // global warp id
    const int nw   = GRID_X * WARPS_PER_BLOCK;                   // 4736 warps

    const int offA = lane * 8;          // row bytes for cols [lane*4 .. lane*4+3]
    const int offB = 256 + lane * 8;    // row bytes for cols [128+lane*4 ..]

    int t = gw;
    if (t >= ntok) return;

    // ---- depth-3 rotating index prefetch ----
    // Warp processes tokens {gw + k*nw}. Slots A,B,C hold indices for the next
    // three tokens; each iteration consumes A and refills the tail.
    const int t1 = (t + nw     < ntok) ? t + nw     : t;
    const int t2 = (t + 2 * nw < ntok) ? t + 2 * nw : t;
    int4 xiA = ldcs_int4(x + (long long)t  * NUM_HASHES);
    int4 xiB = ldcs_int4(x + (long long)t1 * NUM_HASHES);
    int4 xiC = ldcs_int4(x + (long long)t2 * NUM_HASHES);

    #pragma unroll 1
    for (; t < ntok; t += nw) {
        // refill slot 3-ahead (clamped; harmless duplicate load near the tail)
        const int tp = (t + 3 * nw < ntok) ? (t + 3 * nw) : t;
        const int4 xiP = ldcs_int4(x + (long long)tp * NUM_HASHES);

        // per-sample weights (broadcast LDS)
        const float w0 = s_w[xiA.x];
        const float w1 = s_w[xiA.y + 513];
        const float w2 = s_w[xiA.z + 1026];
        const float w3 = s_w[xiA.w + 1539];

        // fp16 row bases (idx = x >> 1; 512 B per row)
        const char* r0 = s_emb + ((xiA.x >> 1) << 9);
        const char* r1 = s_emb + ((xiA.y >> 1) << 9);
        const char* r2 = s_emb + ((xiA.z >> 1) << 9);
        const char* r3 = s_emb + ((xiA.w >> 1) << 9);

        // batch all 8 gather loads (8 outstanding LDS.64)
        uint2 gA0 = *reinterpret_cast<const uint2*>(r0 + offA);
        uint2 gA1 = *reinterpret_cast<const uint2*>(r1 + offA);
        uint2 gA2 = *reinterpret_cast<const uint2*>(r2 + offA);
        uint2 gA3 = *reinterpret_cast<const uint2*>(r3 + offA);
        uint2 gB0 = *reinterpret_cast<const uint2*>(r0 + offB);
        uint2 gB1 = *reinterpret_cast<const uint2*>(r1 + offB);
        uint2 gB2 = *reinterpret_cast<const uint2*>(r2 + offB);
        uint2 gB3 = *reinterpret_cast<const uint2*>(r3 + offB);

        float a0 = 0.f, a1 = 0.f, a2 = 0.f, a3 = 0.f;
        float b0 = 0.f, b1 = 0.f, b2 = 0.f, b3 = 0.f;

        #define ACC(ga, gb, w)                                                    \
        {                                                                         \
            float2 fa0 = __half22float2(*reinterpret_cast<__half2*>(&(ga).x));    \
            float2 fa1 = __half22float2(*reinterpret_cast<__half2*>(&(ga).y));    \
            float2 fb0 = __half22float2(*reinterpret_cast<__half2*>(&(gb).x));    \
            float2 fb1 = __half22float2(*reinterpret_cast<__half2*>(&(gb).y));    \
            a0 += (w) * fa0.x;  a1 += (w) * fa0.y;                                \
            a2 += (w) * fa1.x;  a3 += (w) * fa1.y;                                \
            b0 += (w) * fb0.x;  b1 += (w) * fb0.y;                                \
            b2 += (w) * fb1.x;  b3 += (w) * fb1.y;                                \
        }
        ACC(gA0, gB0, w0)
        ACC(gA1, gB1, w1)
        ACC(gA2, gB2, w2)
        ACC(gA3, gB3, w3)
        #undef ACC

        float* op = out + (long long)t * D + lane * 4;
        stcs_float4(op,       make_float4(a0, a1, a2, a3));
        stcs_float4(op + 128, make_float4(b0, b1, b2, b3));

        // rotate prefetch pipeline
        xiA = xiB;
        xiB = xiC;
        xiC = xiP;
    }
}

extern "C" void kernel_launch(void* const* d_in, const int* in_sizes, int n_in,
                              void* d_out, int out_size)
{
    const int*   x            = (const int*)d_in[0];
    const float* weight_table = (const float*)d_in[1];
    const float* emb_table    = (const float*)d_in[2];
    float*       out          = (float*)d_out;

    const int ntok = in_sizes[0] / NUM_HASHES;   // 65536

    cudaFuncSetAttribute(hash_embedding_kernel,
                         cudaFuncAttributeMaxDynamicSharedMemorySize, SMEM_BYTES);

    hash_embedding_kernel<<<GRID_X, BLOCK_THREADS, SMEM_BYTES>>>(
        x, weight_table, emb_table, out, ntok);
}